// round 2
// baseline (speedup 1.0000x reference)
#include <cuda_runtime.h>
#include <math.h>

#define Hdim 300
#define H3   900
#define NB   2048
#define SEG  48
#define NR   (NB*SEG)

// ---- scratch (device globals: the sanctioned no-alloc path) ----
__device__ float g_padded[(size_t)SEG*NB*Hdim];     // [l][b][h]  118 MB
__device__ float g_xp[2][(size_t)SEG*NB*H3];        // [z][l][b][g] 708 MB
__device__ float g_hp[2][(size_t)NB*H3];            // [z][b][g]
__device__ float g_h[2][NB*Hdim];                   // [z][b][h]
__device__ int   g_counts[NB];
__device__ int   g_offsets[NB];

// ---------------- setup kernels ----------------
__global__ void k_zero_counts() {
    int i = blockIdx.x*blockDim.x + threadIdx.x;
    if (i < NB) g_counts[i] = 0;
}

__global__ void k_count(const int* __restrict__ batch) {
    int i = blockIdx.x*blockDim.x + threadIdx.x;
    if (i < NR) atomicAdd(&g_counts[batch[i]], 1);
}

// one block, 1024 threads: Kogge-Stone inclusive scan over 2048 counts
__global__ void k_scan() {
    __shared__ int s[NB];
    int tid = threadIdx.x;
    s[tid]       = g_counts[tid];
    s[tid+1024]  = g_counts[tid+1024];
    __syncthreads();
    for (int off = 1; off < NB; off <<= 1) {
        int v0 = (tid      >= off) ? s[tid      - off] : 0;
        int v1 = (tid+1024 >= off) ? s[tid+1024 - off] : 0;
        __syncthreads();
        s[tid]      += v0;
        s[tid+1024] += v1;
        __syncthreads();
    }
    g_offsets[tid]      = s[tid]      - g_counts[tid];
    g_offsets[tid+1024] = s[tid+1024] - g_counts[tid+1024];
}

__global__ void k_zero_padded() {
    size_t tot = (size_t)SEG*NB*Hdim;
    for (size_t i = (size_t)blockIdx.x*blockDim.x + threadIdx.x; i < tot;
         i += (size_t)gridDim.x*blockDim.x)
        g_padded[i] = 0.f;
}

// padded[pos][b][:] = relu(x[i] + bias)
__global__ void k_pack(const float* __restrict__ x, const float* __restrict__ bias,
                       const int* __restrict__ batch) {
    int i = blockIdx.x;
    int b = batch[i];
    int pos = i - g_offsets[b];
    const float* xr = x + (size_t)i*Hdim;
    float* dst = g_padded + ((size_t)pos*NB + b)*Hdim;
    for (int j = threadIdx.x; j < Hdim; j += blockDim.x) {
        float v = xr[j] + bias[j];
        dst[j] = v > 0.f ? v : 0.f;
    }
}

// h0[b] = segment_max over raw x; init both directions
__global__ void k_h0(const float* __restrict__ x) {
    int b = blockIdx.x;
    int cnt = g_counts[b], off = g_offsets[b];
    for (int j = threadIdx.x; j < Hdim; j += blockDim.x) {
        float m = -3.402823466e38f;
        for (int r = 0; r < cnt; r++)
            m = fmaxf(m, x[(size_t)(off + r)*Hdim + j]);
        g_h[0][b*Hdim + j] = m;
        g_h[1][b*Hdim + j] = m;
    }
}

// ---------------- SGEMM: C[m,g] = sum_k A[m,k]*W[g,k] + bias[g] ----------------
// mode 0: A = g_padded (M=NR), C = g_xp[z]     (big input projection)
// mode 1: A = g_h[z]   (M=NB), C = g_hp[z]     (recurrent hidden projection)
// 128x128 block tile, K-tile 8, 8x8 per thread, 256 threads, double-buffered smem.
__global__ __launch_bounds__(256, 2) void k_gemm(int mode,
    const float* __restrict__ W0, const float* __restrict__ W1,
    const float* __restrict__ b0, const float* __restrict__ b1)
{
    const int K = Hdim;            // 300
    const int Ncols = H3;          // 900
    const int KT = (K + 7) / 8;    // 38

    int z = blockIdx.z;
    const float* W    = z ? W1 : W0;
    const float* bias = z ? b1 : b0;
    const float* A = (mode == 0) ? g_padded : g_h[z];
    float*       C = (mode == 0) ? g_xp[z]  : g_hp[z];

    __shared__ __align__(16) float As[2][8][128];
    __shared__ __align__(16) float Bs[2][8][128];

    int tid = threadIdx.x;
    int bm = blockIdx.y * 128, bn = blockIdx.x * 128;
    int lr = tid >> 1;             // 0..127 : tile row (A: m, B: n)
    int lc = (tid & 1) * 4;        // 0 or 4 : k offset
    int ty = tid >> 4, tx = tid & 15;

    float acc[8][8];
    #pragma unroll
    for (int i = 0; i < 8; i++)
        #pragma unroll
        for (int j = 0; j < 8; j++) acc[i][j] = 0.f;

    const float* Arow = A + (size_t)(bm + lr)*K;
    int gcol = bn + lr;
    bool wok = gcol < Ncols;
    const float* Wrow = W + (size_t)(wok ? gcol : 0)*K;

    float pa[4], pb[4];
    auto FETCH = [&](int kt) {
        int k0 = kt*8 + lc;
        #pragma unroll
        for (int i = 0; i < 4; i++) {
            int k = k0 + i;
            bool kok = k < K;
            pa[i] = kok ? Arow[k] : 0.f;
            pb[i] = (kok && wok) ? Wrow[k] : 0.f;
        }
    };
    auto STORE = [&](int buf) {
        #pragma unroll
        for (int i = 0; i < 4; i++) {
            As[buf][lc + i][lr] = pa[i];
            Bs[buf][lc + i][lr] = pb[i];
        }
    };

    FETCH(0); STORE(0); __syncthreads();

    for (int kt = 0; kt < KT; kt++) {
        int buf = kt & 1;
        if (kt + 1 < KT) FETCH(kt + 1);
        #pragma unroll
        for (int kk = 0; kk < 8; kk++) {
            float4 a0  = *(const float4*)&As[buf][kk][ty*8];
            float4 a1  = *(const float4*)&As[buf][kk][ty*8 + 4];
            float4 bb0 = *(const float4*)&Bs[buf][kk][tx*8];
            float4 bb1 = *(const float4*)&Bs[buf][kk][tx*8 + 4];
            float av[8] = {a0.x,a0.y,a0.z,a0.w,a1.x,a1.y,a1.z,a1.w};
            float bv[8] = {bb0.x,bb0.y,bb0.z,bb0.w,bb1.x,bb1.y,bb1.z,bb1.w};
            #pragma unroll
            for (int i = 0; i < 8; i++)
                #pragma unroll
                for (int j = 0; j < 8; j++)
                    acc[i][j] = fmaf(av[i], bv[j], acc[i][j]);
        }
        if (kt + 1 < KT) STORE(buf ^ 1);
        __syncthreads();
    }

    int row0 = bm + ty*8;
    int col0 = bn + tx*8;
    #pragma unroll
    for (int i = 0; i < 8; i++) {
        float* crow = C + (size_t)(row0 + i)*Ncols;
        #pragma unroll
        for (int j = 0; j < 8; j++) {
            int c = col0 + j;
            if (c < Ncols) crow[c] = acc[i][j] + bias[c];
        }
    }
}

// ---------------- gate fusion per step ----------------
__global__ void k_gate(int s, float* __restrict__ out) {
    int z = blockIdx.y;
    int idx = blockIdx.x*blockDim.x + threadIdx.x;
    if (idx >= NB*Hdim) return;
    int b = idx / Hdim;
    int j = idx - b*Hdim;
    int t = z ? (SEG - 1 - s) : s;

    const float* xp = g_xp[z] + ((size_t)t*NB + b)*H3;
    const float* hp = g_hp[z] + (size_t)b*H3;
    float h = g_h[z][idx];

    float r  = 1.f/(1.f + expf(-(xp[j]          + hp[j])));
    float zg = 1.f/(1.f + expf(-(xp[Hdim + j]   + hp[Hdim + j])));
    float nn = tanhf(xp[2*Hdim + j] + r*hp[2*Hdim + j]);
    float hnew = (1.f - zg)*nn + zg*h;

    g_h[z][idx] = hnew;
    if (t < g_counts[b]) {
        out[(size_t)(g_offsets[b] + t)*(2*Hdim) + z*Hdim + j] = hnew;
    }
}

// ---------------- launch ----------------
extern "C" void kernel_launch(void* const* d_in, const int* in_sizes, int n_in,
                              void* d_out, int out_size) {
    const float* x      = (const float*)d_in[0];
    const int*   batch  = (const int*)  d_in[1];
    // d_in[2]=num_moles, d_in[3]=max_len (fixed: 2048 / 48)
    const float* bias   = (const float*)d_in[4];
    const float* w_ih_f = (const float*)d_in[5];
    const float* w_hh_f = (const float*)d_in[6];
    const float* b_ih_f = (const float*)d_in[7];
    const float* b_hh_f = (const float*)d_in[8];
    const float* w_ih_b = (const float*)d_in[9];
    const float* w_hh_b = (const float*)d_in[10];
    const float* b_ih_b = (const float*)d_in[11];
    const float* b_hh_b = (const float*)d_in[12];
    float* out = (float*)d_out;

    k_zero_counts<<<(NB + 255)/256, 256>>>();
    k_count<<<(NR + 255)/256, 256>>>(batch);
    k_scan<<<1, 1024>>>();
    k_zero_padded<<<4096, 256>>>();
    k_pack<<<NR, 128>>>(x, bias, batch);
    k_h0<<<NB, 128>>>(x);

    // big input-projection GEMM, both directions (z=0/1)
    dim3 gbig((H3 + 127)/128, NR/128, 2);   // 8 x 768 x 2
    k_gemm<<<gbig, 256>>>(0, w_ih_f, w_ih_b, b_ih_f, b_ih_b);

    dim3 grec((H3 + 127)/128, NB/128, 2);   // 8 x 16 x 2
    dim3 ggate((NB*Hdim + 255)/256, 2);
    for (int s = 0; s < SEG; s++) {
        k_gemm<<<grec, 256>>>(1, w_hh_f, w_hh_b, b_hh_f, b_hh_b);
        k_gate<<<ggate, 256>>>(s, out);
    }
}